// round 5
// baseline (speedup 1.0000x reference)
#include <cuda_runtime.h>

#define UNITS 64
#define BATCH 64
#define NZ 448            // gate output cols (192 r + 256 z)
#define NT 32             // n-tile width for phase 1
#define NP1 14            // phase-1 tiles per cell (448/32)
#define NP2 4             // phase-2 tiles per cell (64 b / 16)
#define GRID 148
#define TPB 256
#define QS 68             // padded row stride for q_s [k][b]
#define DIAGS 63
#define TOTAL_ITEMS (18*1024)
// smem: U_s 16384 + q_s 256*68=17408 + w2_s 16384 floats = 50176 floats
#define SMEM_FLOATS 50176
#define SMEM_BYTES (SMEM_FLOATS*4)

// ---------------- global scratch ----------------
__device__ float g_states [33*33*BATCH*UNITS];  // h at [i][j][b][u]
__device__ float g_statesT[33*33*BATCH*UNITS];  // h at [i][j][u][b]
__device__ float g_xT[1024*64*64];              // inputs transposed: [t][c][b]
__device__ float g_RZ[32*NZ*BATCH];             // per-row-slot scratch [i][n][b]
__device__ int   g_p1done[1024];
__device__ int   g_hdone [1024];

// ---------------- f32x2 helpers ----------------
__device__ __forceinline__ unsigned long long pack2(float x, float y) {
    unsigned long long r;
    asm("mov.b64 %0, {%1,%2};" : "=l"(r) : "f"(x), "f"(y));
    return r;
}
__device__ __forceinline__ void unpack2(unsigned long long v, float& x, float& y) {
    asm("mov.b64 {%0,%1}, %2;" : "=f"(x), "=f"(y) : "l"(v));
}
__device__ __forceinline__ unsigned long long ffma2(unsigned long long a,
                                                    unsigned long long b,
                                                    unsigned long long c) {
    unsigned long long d;
    asm("fma.rn.f32x2 %0, %1, %2, %3;" : "=l"(d) : "l"(a), "l"(b), "l"(c));
    return d;
}
__device__ __forceinline__ unsigned long long add2(unsigned long long a,
                                                   unsigned long long b) {
    unsigned long long d;
    asm("add.rn.f32x2 %0, %1, %2;" : "=l"(d) : "l"(a), "l"(b));
    return d;
}

// ---------------- sync helpers ----------------
__device__ __forceinline__ int ld_acq(const int* p) {
    int v;
    asm volatile("ld.global.acquire.gpu.b32 %0, [%1];" : "=r"(v) : "l"(p) : "memory");
    return v;
}
__device__ __forceinline__ void spin_ge(const int* p, int v) {
    while (ld_acq(p) < v) { __nanosleep(20); }
}

// ---------------- init ----------------
__global__ void init_kernel(const float* __restrict__ in) {
    int tid = blockIdx.x * blockDim.x + threadIdx.x;
    int stride = gridDim.x * blockDim.x;
    const int NS = 33*33*BATCH*UNITS;
    for (int idx = tid; idx < NS; idx += stride) {
        g_states[idx] = 0.f;
        g_statesT[idx] = 0.f;
    }
    for (int idx = tid; idx < 2048; idx += stride) {
        if (idx < 1024) g_p1done[idx] = 0; else g_hdone[idx - 1024] = 0;
    }
    const int NX = 1024*64*64;
    for (int idx = tid; idx < NX; idx += stride) {
        int b = idx & 63;
        int c = (idx >> 6) & 63;
        int t = idx >> 12;
        g_xT[idx] = in[(b*64 + c)*1024 + t];
    }
}

// ---------------- main persistent dataflow kernel ----------------
__global__ __launch_bounds__(TPB, 1)
void gru_kernel(const float* __restrict__ W, const float* __restrict__ U_rec,
                const float* __restrict__ bias, const float* __restrict__ W_ij,
                float* __restrict__ out)
{
    extern __shared__ float sm[];
    const int tid = threadIdx.x;

    float* U_s  = sm;           // [256][64] persistent: rows 0..191 U_rec, 192..255 W_ij
    float* q_s  = sm + 16384;   // [256][QS] phase-1 (aliased by m_s/h_s in phase-2)
    float* w2_s = sm + 16384 + 17408;  // [256][64] phase-1 W tile, lane-duplicated pairs

    // load U once per block (constant across all items)
    {
        const float4* up  = (const float4*)U_rec;   // 3072 f4
        const float4* wij = (const float4*)W_ij;    // 1024 f4
        for (int e = tid; e < 4096; e += TPB) {
            float4 v = (e < 3072) ? up[e] : wij[e - 3072];
            *(float4*)&U_s[e << 2] = v;
        }
    }
    __syncthreads();

    for (int item = blockIdx.x; item < TOTAL_ITEMS; item += gridDim.x) {
        // ---- decode item -> (diagonal d, phase, cell, tile) ----
        int d = 0, base = 0, nd = 1, i0 = 0;
        for (d = 0; d < DIAGS; d++) {
            i0 = (d > 31) ? (d - 31) : 0;
            int i1 = (d < 31) ? d : 31;
            nd = i1 - i0 + 1;
            int sz = 18 * nd;
            if (item < base + sz) break;
            base += sz;
        }
        int local = item - base;

        if (local < NP1 * nd) {
            // ========== PHASE 1: gate GEMM tile (64b x 32n x 256k), f32x2 ==========
            int ci = local / NP1, nt = local % NP1;
            int i = i0 + ci, j = d - i;

            // stage W tile (dependency-free) BEFORE the spin.
            // cols [nt*32, nt*32+32), duplicated: w2_s[k][4p..4p+3] = (w0,w0,w1,w1)
            {
                const float2* wp = (const float2*)(W + nt*NT);   // row stride 224 f2
                for (int e = tid; e < 4096; e += TPB) {
                    int k = e >> 4, p = e & 15;
                    float2 w = wp[k*224 + p];
                    float4 v = make_float4(w.x, w.x, w.y, w.y);
                    *(float4*)&w2_s[(k << 6) + (p << 2)] = v;
                }
            }

            if (tid == 0) {
                if (i > 0 && j > 0) spin_ge(&g_hdone[(i-1)*32 + (j-1)], NP2);
                if (i > 0)          spin_ge(&g_hdone[(i-1)*32 + j    ], NP2);
                if (j > 0)          spin_ge(&g_hdone[ i   *32 + (j-1)], NP2);
            }
            __syncthreads();

            // stage q = [h_top, h_left, h_diag, s_ij], layout [k][b]
            const float* src0 = &g_statesT[((size_t)( i   *33 + (j+1)))*4096];  // h_top
            const float* src1 = &g_statesT[((size_t)((i+1)*33 +  j   ))*4096];  // h_left
            const float* src2 = &g_statesT[((size_t)( i   *33 +  j   ))*4096];  // h_diag
            const float* src3 = &g_xT[(size_t)(i*32 + j)*4096];                 // s_ij
            const float* srcs[4] = {src0, src1, src2, src3};
            #pragma unroll
            for (int p = 0; p < 4; p++) {
                const float4* sp = (const float4*)srcs[p];
                for (int e = tid; e < 1024; e += TPB) {
                    int u = e >> 4, b4 = (e & 15) << 2;
                    *(float4*)&q_s[(p*64 + u)*QS + b4] = sp[e];
                }
            }
            __syncthreads();

            // thread tile: 4 b x 2 n.  nx = n-group (16), by = b-group (16)
            const int nx = tid & 15, by = tid >> 4;
            unsigned long long a_n0_b01 = 0ull, a_n0_b23 = 0ull;
            unsigned long long a_n1_b01 = 0ull, a_n1_b23 = 0ull;
            const float* qp = q_s  + (by << 2);
            const float* wp = w2_s + (nx << 2);
            #pragma unroll 4
            for (int k = 0; k < 256; k++) {
                ulonglong2 qv = *(const ulonglong2*)(qp + k*QS);      // (b0,b1),(b2,b3)
                ulonglong2 wv = *(const ulonglong2*)(wp + (k << 6));  // (w0,w0),(w1,w1)
                a_n0_b01 = ffma2(qv.x, wv.x, a_n0_b01);
                a_n0_b23 = ffma2(qv.y, wv.x, a_n0_b23);
                a_n1_b01 = ffma2(qv.x, wv.y, a_n1_b01);
                a_n1_b23 = ffma2(qv.y, wv.y, a_n1_b23);
            }
            int n0 = nt*NT + (nx << 1);
            unsigned long long bb0 = pack2(bias[n0],   bias[n0]);
            unsigned long long bb1 = pack2(bias[n0+1], bias[n0+1]);
            a_n0_b01 = add2(a_n0_b01, bb0);  a_n0_b23 = add2(a_n0_b23, bb0);
            a_n1_b01 = add2(a_n1_b01, bb1);  a_n1_b23 = add2(a_n1_b23, bb1);

            float* rz = &g_RZ[(size_t)i * NZ * 64];
            int bb = by << 2;
            float4 v0, v1;
            unpack2(a_n0_b01, v0.x, v0.y); unpack2(a_n0_b23, v0.z, v0.w);
            unpack2(a_n1_b01, v1.x, v1.y); unpack2(a_n1_b23, v1.z, v1.w);
            *(float4*)&rz[(n0  )*64 + bb] = v0;
            *(float4*)&rz[(n0+1)*64 + bb] = v1;

            __threadfence();
            __syncthreads();
            if (tid == 0) atomicAdd(&g_p1done[i*32 + j], 1);
        } else {
            // ========== PHASE 2: update GEMM + gates (16b x 64u x 256k) ==========
            int l2 = local - NP1*nd;
            int ci = l2 / NP2, bt = l2 % NP2;
            int i = i0 + ci, j = d - i;

            if (tid == 0) spin_ge(&g_p1done[i*32 + j], NP1);
            __syncthreads();

            float* m_s = q_s;            // [256][16]
            float* h_s = q_s + 4096;     // [16][65]

            const float* rz  = &g_RZ[(size_t)i * NZ * 64];
            const float* hlT = &g_statesT[((size_t)((i+1)*33 +  j   ))*4096];
            const float* htT = &g_statesT[((size_t)( i   *33 + (j+1)))*4096];
            const float* hdT = &g_statesT[((size_t)( i   *33 +  j   ))*4096];
            const float* xs  = &g_xT[(size_t)(i*32 + j)*4096];

            // m = r * [h_left, h_top, h_diag] (rows 0..191), s_ij (rows 192..255)
            for (int e = tid; e < 4096; e += TPB) {
                int k = e >> 4, b = e & 15;
                int ba = (bt << 4) + b;
                float v;
                if (k < 192) {
                    int g = k >> 6, kk = k & 63;
                    const float* hT = (g == 0) ? hlT : (g == 1) ? htT : hdT;
                    float h = hT[(kk << 6) + ba];
                    float r = rz[(k << 6) + ba];
                    r = 1.f / (1.f + __expf(-r));
                    v = r * h;
                } else {
                    v = xs[((k - 192) << 6) + ba];
                }
                m_s[(k << 4) + b] = v;
            }
            __syncthreads();

            const int u = tid & 63, bsub = tid >> 6;  // 4 consecutive b per thread
            float bj = bias[448 + u];
            float4 acc = {bj, bj, bj, bj};
            const float* mp = m_s + (bsub << 2);
            #pragma unroll 4
            for (int k = 0; k < 256; k++) {
                float  un = U_s[(k << 6) + u];
                float4 mv = *(const float4*)(mp + (k << 4));
                acc.x += mv.x*un; acc.y += mv.y*un; acc.z += mv.z*un; acc.w += mv.w*un;
            }

            const float* hl = &g_states[((size_t)((i+1)*33 +  j   ))*4096];
            const float* ht = &g_states[((size_t)( i   *33 + (j+1)))*4096];
            const float* hd = &g_states[((size_t)( i   *33 +  j   ))*4096];
            float* hout  = &g_states [((size_t)((i+1)*33 + (j+1)))*4096];
            const float* zb = rz + 192*64;
            float accs[4] = {acc.x, acc.y, acc.z, acc.w};
            bool last = (i == 31) && (j == 31);
            #pragma unroll
            for (int q = 0; q < 4; q++) {
                int bl = (bsub << 2) + q;
                int ba = (bt << 4) + bl;
                float z0 = zb[( u        << 6) + ba];   // zi
                float z1 = zb[((64 + u)  << 6) + ba];   // zl
                float z2 = zb[((128 + u) << 6) + ba];   // zt
                float z3 = zb[((192 + u) << 6) + ba];   // zd
                float mx = fmaxf(fmaxf(z0, z1), fmaxf(z2, z3));
                float e0 = __expf(z0 - mx), e1 = __expf(z1 - mx);
                float e2 = __expf(z2 - mx), e3 = __expf(z3 - mx);
                float inv = 1.f / (e0 + e1 + e2 + e3);
                float hh = tanhf(accs[q]);
                float vl = hl[(ba << 6) + u];
                float vt = ht[(ba << 6) + u];
                float vd = hd[(ba << 6) + u];
                float h  = (e1*vl + e2*vt + e3*vd + e0*hh) * inv;
                hout[(ba << 6) + u] = h;
                h_s[bl*65 + u] = h;
                if (last) out[(ba << 6) + u] = h;
            }
            __syncthreads();
            float* houtT = &g_statesT[((size_t)((i+1)*33 + (j+1)))*4096];
            for (int e = tid; e < 1024; e += TPB) {
                int b = e & 15, uu = e >> 4;
                houtT[(uu << 6) + (bt << 4) + b] = h_s[b*65 + uu];
            }
            __threadfence();
            __syncthreads();
            if (tid == 0) atomicAdd(&g_hdone[i*32 + j], 1);
        }
    }
}

extern "C" void kernel_launch(void* const* d_in, const int* in_sizes, int n_in,
                              void* d_out, int out_size) {
    const float* inputs = (const float*)d_in[0];
    const float* W      = (const float*)d_in[1];
    const float* U_rec  = (const float*)d_in[2];
    const float* bias   = (const float*)d_in[3];
    const float* W_ij   = (const float*)d_in[4];
    float* out = (float*)d_out;

    cudaFuncSetAttribute(gru_kernel, cudaFuncAttributeMaxDynamicSharedMemorySize, SMEM_BYTES);

    init_kernel<<<512, 256>>>(inputs);
    gru_kernel<<<GRID, TPB, SMEM_BYTES>>>(W, U_rec, bias, W_ij, out);
}

// round 10
// speedup vs baseline: 1.1395x; 1.1395x over previous
#include <cuda_runtime.h>

#define UNITS 64
#define BATCH 64
#define NZ 448            // gate output cols (192 r + 256 z)
#define NT 64             // n-tile width for phase 1
#define NP1 7             // phase-1 tiles per cell (448/64)
#define NP2 4             // phase-2 tiles per cell (64 b / 16)
#define GRID 148
#define TPB 256
#define QS 68             // padded row stride for q_s [k][b]
#define DIAGS 63
#define ITEMS_PER_CELL 11
#define TOTAL_ITEMS (ITEMS_PER_CELL*1024)
// smem: q_s 256*68=17408 + w2_s 256*128=32768 floats = 50176 floats = 200704 B
#define SMEM_FLOATS 50176
#define SMEM_BYTES (SMEM_FLOATS*4)

// ---------------- global scratch ----------------
__device__ float g_states [33*33*BATCH*UNITS];  // h at [i][j][b][u]
__device__ float g_statesT[33*33*BATCH*UNITS];  // h at [i][j][u][b]
__device__ float g_xT[1024*64*64];              // inputs transposed: [t][c][b]
__device__ float g_RZ[32*NZ*BATCH];             // per-row-slot scratch [i][n][b]
__device__ int   g_p1done[1024];
__device__ int   g_hdone [1024];
__device__ int   g_next;

// ---------------- f32x2 helpers ----------------
__device__ __forceinline__ unsigned long long pack2(float x, float y) {
    unsigned long long r;
    asm("mov.b64 %0, {%1,%2};" : "=l"(r) : "f"(x), "f"(y));
    return r;
}
__device__ __forceinline__ void unpack2(unsigned long long v, float& x, float& y) {
    asm("mov.b64 {%0,%1}, %2;" : "=f"(x), "=f"(y) : "l"(v));
}
__device__ __forceinline__ unsigned long long ffma2(unsigned long long a,
                                                    unsigned long long b,
                                                    unsigned long long c) {
    unsigned long long d;
    asm("fma.rn.f32x2 %0, %1, %2, %3;" : "=l"(d) : "l"(a), "l"(b), "l"(c));
    return d;
}
__device__ __forceinline__ unsigned long long add2(unsigned long long a,
                                                   unsigned long long b) {
    unsigned long long d;
    asm("add.rn.f32x2 %0, %1, %2;" : "=l"(d) : "l"(a), "l"(b));
    return d;
}

// ---------------- sync helpers ----------------
__device__ __forceinline__ int ld_acq(const int* p) {
    int v;
    asm volatile("ld.global.acquire.gpu.b32 %0, [%1];" : "=r"(v) : "l"(p) : "memory");
    return v;
}
__device__ __forceinline__ void spin_ge(const int* p, int v) {
    while (ld_acq(p) < v) { __nanosleep(20); }
}

// ---------------- init ----------------
__global__ void init_kernel(const float* __restrict__ in) {
    int tid = blockIdx.x * blockDim.x + threadIdx.x;
    int stride = gridDim.x * blockDim.x;
    if (tid == 0) g_next = 0;
    const int NS = 33*33*BATCH*UNITS;
    for (int idx = tid; idx < NS; idx += stride) {
        g_states[idx] = 0.f;
        g_statesT[idx] = 0.f;
    }
    for (int idx = tid; idx < 2048; idx += stride) {
        if (idx < 1024) g_p1done[idx] = 0; else g_hdone[idx - 1024] = 0;
    }
    const int NX = 1024*64*64;
    for (int idx = tid; idx < NX; idx += stride) {
        int b = idx & 63;
        int c = (idx >> 6) & 63;
        int t = idx >> 12;
        g_xT[idx] = in[(b*64 + c)*1024 + t];
    }
}

// ---------------- main persistent dataflow kernel ----------------
__global__ __launch_bounds__(TPB, 1)
void gru_kernel(const float* __restrict__ W, const float* __restrict__ U_rec,
                const float* __restrict__ bias, const float* __restrict__ W_ij,
                float* __restrict__ out)
{
    extern __shared__ float sm[];
    __shared__ int s_item;
    const int tid = threadIdx.x;

    float* q_s  = sm;           // [256][QS]  phase-1 q tile
    float* w2_s = sm + 17408;   // [256][128] phase-1 W tile (lane-duplicated pairs)
    // phase-2 aliases:
    float* U_s2 = sm;           // [256][64]  U_rec rows 0..191, W_ij rows 192..255
    float* m_s  = sm + 17408;          // [256][16]
    float* h_s  = sm + 17408 + 4096;   // [16][65]

    for (;;) {
        if (tid == 0) s_item = atomicAdd(&g_next, 1);
        __syncthreads();
        int item = s_item;
        if (item >= TOTAL_ITEMS) break;

        // ---- decode item -> (diagonal d, phase, cell, tile) ----
        int d = 0, base = 0, nd = 1, i0 = 0;
        for (d = 0; d < DIAGS; d++) {
            i0 = (d > 31) ? (d - 31) : 0;
            int i1 = (d < 31) ? d : 31;
            nd = i1 - i0 + 1;
            int sz = ITEMS_PER_CELL * nd;
            if (item < base + sz) break;
            base += sz;
        }
        int local = item - base;

        if (local < NP1 * nd) {
            // ========== PHASE 1: gate GEMM tile (64b x 64n x 256k), f32x2 ==========
            int ci = local / NP1, nt = local % NP1;
            int i = i0 + ci, j = d - i;

            // stage W tile (dependency-free) BEFORE the spin.
            // cols [nt*64, nt*64+64): w2_s[k][4p..4p+3] = (w_{2p},w_{2p},w_{2p+1},w_{2p+1})
            {
                const float2* wp = (const float2*)(W + nt*NT);   // row stride 224 f2
                for (int e = tid; e < 8192; e += TPB) {
                    int k = e >> 5, p = e & 31;
                    float2 w = wp[k*224 + p];
                    *(float4*)&w2_s[(k << 7) + (p << 2)] = make_float4(w.x, w.x, w.y, w.y);
                }
            }

            if (tid == 0) {
                if (i > 0 && j > 0) spin_ge(&g_hdone[(i-1)*32 + (j-1)], NP2);
                if (i > 0)          spin_ge(&g_hdone[(i-1)*32 + j    ], NP2);
                if (j > 0)          spin_ge(&g_hdone[ i   *32 + (j-1)], NP2);
            }
            __syncthreads();

            // stage q = [h_top, h_left, h_diag, s_ij], layout [k][b]
            const float* src0 = &g_statesT[((size_t)( i   *33 + (j+1)))*4096];  // h_top
            const float* src1 = &g_statesT[((size_t)((i+1)*33 +  j   ))*4096];  // h_left
            const float* src2 = &g_statesT[((size_t)( i   *33 +  j   ))*4096];  // h_diag
            const float* src3 = &g_xT[(size_t)(i*32 + j)*4096];                 // s_ij
            const float* srcs[4] = {src0, src1, src2, src3};
            #pragma unroll
            for (int p = 0; p < 4; p++) {
                const float4* sp = (const float4*)srcs[p];
                for (int e = tid; e < 1024; e += TPB) {
                    int u = e >> 4, b4 = (e & 15) << 2;
                    *(float4*)&q_s[(p*64 + u)*QS + b4] = sp[e];
                }
            }
            __syncthreads();

            // thread tile: 4 b x 4 n.  warp covers 8 bg x 4 ng (smem-friendly)
            const int bg = (tid & 7) | ((tid >> 4) & 8);   // 0..15, bit3 from tid bit7
            const int ng = (tid >> 3) & 15;                // 0..15
            unsigned long long a00=0ull,a01=0ull,a10=0ull,a11=0ull;
            unsigned long long a20=0ull,a21=0ull,a30=0ull,a31=0ull;
            const float* qp  = q_s  + (bg << 2);
            const float* wpS = w2_s + (ng << 3);
            #pragma unroll 4
            for (int k = 0; k < 256; k++) {
                ulonglong2 qv = *(const ulonglong2*)(qp + k*QS);          // (b0,b1),(b2,b3)
                ulonglong2 w0 = *(const ulonglong2*)(wpS + (k << 7));     // (n0,n0),(n1,n1)
                ulonglong2 w1 = *(const ulonglong2*)(wpS + (k << 7) + 4); // (n2,n2),(n3,n3)
                a00 = ffma2(qv.x, w0.x, a00);  a01 = ffma2(qv.y, w0.x, a01);
                a10 = ffma2(qv.x, w0.y, a10);  a11 = ffma2(qv.y, w0.y, a11);
                a20 = ffma2(qv.x, w1.x, a20);  a21 = ffma2(qv.y, w1.x, a21);
                a30 = ffma2(qv.x, w1.y, a30);  a31 = ffma2(qv.y, w1.y, a31);
            }
            int n0 = nt*NT + (ng << 2);
            int bb = bg << 2;
            float* rz = &g_RZ[(size_t)i * NZ * 64];
            {
                float4 v;
                unsigned long long bbias;
                bbias = pack2(bias[n0+0], bias[n0+0]);
                unpack2(add2(a00, bbias), v.x, v.y); unpack2(add2(a01, bbias), v.z, v.w);
                *(float4*)&rz[(n0+0)*64 + bb] = v;
                bbias = pack2(bias[n0+1], bias[n0+1]);
                unpack2(add2(a10, bbias), v.x, v.y); unpack2(add2(a11, bbias), v.z, v.w);
                *(float4*)&rz[(n0+1)*64 + bb] = v;
                bbias = pack2(bias[n0+2], bias[n0+2]);
                unpack2(add2(a20, bbias), v.x, v.y); unpack2(add2(a21, bbias), v.z, v.w);
                *(float4*)&rz[(n0+2)*64 + bb] = v;
                bbias = pack2(bias[n0+3], bias[n0+3]);
                unpack2(add2(a30, bbias), v.x, v.y); unpack2(add2(a31, bbias), v.z, v.w);
                *(float4*)&rz[(n0+3)*64 + bb] = v;
            }

            __threadfence();
            __syncthreads();
            if (tid == 0) atomicAdd(&g_p1done[i*32 + j], 1);
        } else {
            // ========== PHASE 2: update GEMM + gates (16b x 64u x 256k) ==========
            int l2 = local - NP1*nd;
            int ci = l2 / NP2, bt = l2 % NP2;
            int i = i0 + ci, j = d - i;

            // stage U (dependency-free) BEFORE the spin
            {
                const float4* up  = (const float4*)U_rec;   // 3072 f4
                const float4* wij = (const float4*)W_ij;    // 1024 f4
                for (int e = tid; e < 4096; e += TPB) {
                    float4 v = (e < 3072) ? up[e] : wij[e - 3072];
                    *(float4*)&U_s2[e << 2] = v;
                }
            }

            if (tid == 0) spin_ge(&g_p1done[i*32 + j], NP1);
            __syncthreads();

            const float* rz  = &g_RZ[(size_t)i * NZ * 64];
            const float* hlT = &g_statesT[((size_t)((i+1)*33 +  j   ))*4096];
            const float* htT = &g_statesT[((size_t)( i   *33 + (j+1)))*4096];
            const float* hdT = &g_statesT[((size_t)( i   *33 +  j   ))*4096];
            const float* xs  = &g_xT[(size_t)(i*32 + j)*4096];

            // m = r * [h_left, h_top, h_diag] (rows 0..191), s_ij (rows 192..255)
            for (int e = tid; e < 4096; e += TPB) {
                int k = e >> 4, b = e & 15;
                int ba = (bt << 4) + b;
                float v;
                if (k < 192) {
                    int g = k >> 6, kk = k & 63;
                    const float* hT = (g == 0) ? hlT : (g == 1) ? htT : hdT;
                    float h = hT[(kk << 6) + ba];
                    float r = rz[(k << 6) + ba];
                    r = 1.f / (1.f + __expf(-r));
                    v = r * h;
                } else {
                    v = xs[((k - 192) << 6) + ba];
                }
                m_s[(k << 4) + b] = v;
            }
            __syncthreads();

            const int u = tid & 63, bsub = tid >> 6;  // 4 consecutive b per thread
            float bj = bias[448 + u];
            float4 acc = {bj, bj, bj, bj};
            const float* mp = m_s + (bsub << 2);
            #pragma unroll 4
            for (int k = 0; k < 256; k++) {
                float  un = U_s2[(k << 6) + u];
                float4 mv = *(const float4*)(mp + (k << 4));
                acc.x += mv.x*un; acc.y += mv.y*un; acc.z += mv.z*un; acc.w += mv.w*un;
            }

            const float* hl = &g_states[((size_t)((i+1)*33 +  j   ))*4096];
            const float* ht = &g_states[((size_t)( i   *33 + (j+1)))*4096];
            const float* hd = &g_states[((size_t)( i   *33 +  j   ))*4096];
            float* hout  = &g_states [((size_t)((i+1)*33 + (j+1)))*4096];
            const float* zb = rz + 192*64;
            float accs[4] = {acc.x, acc.y, acc.z, acc.w};
            bool last = (i == 31) && (j == 31);
            #pragma unroll
            for (int q = 0; q < 4; q++) {
                int bl = (bsub << 2) + q;
                int ba = (bt << 4) + bl;
                float z0 = zb[( u        << 6) + ba];   // zi
                float z1 = zb[((64 + u)  << 6) + ba];   // zl
                float z2 = zb[((128 + u) << 6) + ba];   // zt
                float z3 = zb[((192 + u) << 6) + ba];   // zd
                float mx = fmaxf(fmaxf(z0, z1), fmaxf(z2, z3));
                float e0 = __expf(z0 - mx), e1 = __expf(z1 - mx);
                float e2 = __expf(z2 - mx), e3 = __expf(z3 - mx);
                float inv = 1.f / (e0 + e1 + e2 + e3);
                float hh = tanhf(accs[q]);
                float vl = hl[(ba << 6) + u];
                float vt = ht[(ba << 6) + u];
                float vd = hd[(ba << 6) + u];
                float h  = (e1*vl + e2*vt + e3*vd + e0*hh) * inv;
                hout[(ba << 6) + u] = h;
                h_s[bl*65 + u] = h;
                if (last) out[(ba << 6) + u] = h;
            }
            __syncthreads();
            float* houtT = &g_statesT[((size_t)((i+1)*33 + (j+1)))*4096];
            for (int e = tid; e < 1024; e += TPB) {
                int b = e & 15, uu = e >> 4;
                houtT[(uu << 6) + (bt << 4) + b] = h_s[b*65 + uu];
            }
            __threadfence();
            __syncthreads();
            if (tid == 0) atomicAdd(&g_hdone[i*32 + j], 1);
        }
    }
}

extern "C" void kernel_launch(void* const* d_in, const int* in_sizes, int n_in,
                              void* d_out, int out_size) {
    const float* inputs = (const float*)d_in[0];
    const float* W      = (const float*)d_in[1];
    const float* U_rec  = (const float*)d_in[2];
    const float* bias   = (const float*)d_in[3];
    const float* W_ij   = (const float*)d_in[4];
    float* out = (float*)d_out;

    cudaFuncSetAttribute(gru_kernel, cudaFuncAttributeMaxDynamicSharedMemorySize, SMEM_BYTES);

    init_kernel<<<512, 256>>>(inputs);
    gru_kernel<<<GRID, TPB, SMEM_BYTES>>>(W, U_rec, bias, W_ij, out);
}

// round 12
// speedup vs baseline: 1.1429x; 1.0030x over previous
#include <cuda_runtime.h>

#define UNITS 64
#define BATCH 64
#define NZ 448            // gate output cols (192 r + 256 z)
#define NT 32             // n-tile width for phase 1
#define NP1 14            // phase-1 tiles per cell (448/32)
#define NP2 4             // phase-2 tiles per cell (64 b / 16)
#define TPB 256
#define QS 68             // padded row stride for q_s [k][b]
#define DIAGS 63
#define ITEMS_PER_CELL 18
#define TOTAL_ITEMS (ITEMS_PER_CELL*1024)
// smem: q_s 256*68=17408 + w_s 256*32=8192 floats = 25600 floats = 102400 B (occ-2 capable)
#define SMEM_FLOATS 25600
#define SMEM_BYTES (SMEM_FLOATS*4)

// ---------------- global scratch ----------------
__device__ float g_states [33*33*BATCH*UNITS];  // h at [i][j][b][u]
__device__ float g_statesT[33*33*BATCH*UNITS];  // h at [i][j][u][b]
__device__ float g_xT[1024*64*64];              // inputs transposed: [t][c][b]
__device__ float g_RZ[32*NZ*BATCH];             // per-row-slot scratch [i][n][b]
__device__ int   g_p1done[1024];
__device__ int   g_hdone [1024];
__device__ int   g_next;

// ---------------- f32x2 helpers ----------------
__device__ __forceinline__ unsigned long long pack2(float x, float y) {
    unsigned long long r;
    asm("mov.b64 %0, {%1,%2};" : "=l"(r) : "f"(x), "f"(y));
    return r;
}
__device__ __forceinline__ void unpack2(unsigned long long v, float& x, float& y) {
    asm("mov.b64 {%0,%1}, %2;" : "=f"(x), "=f"(y) : "l"(v));
}
__device__ __forceinline__ unsigned long long ffma2(unsigned long long a,
                                                    unsigned long long b,
                                                    unsigned long long c) {
    unsigned long long d;
    asm("fma.rn.f32x2 %0, %1, %2, %3;" : "=l"(d) : "l"(a), "l"(b), "l"(c));
    return d;
}
__device__ __forceinline__ unsigned long long add2(unsigned long long a,
                                                   unsigned long long b) {
    unsigned long long d;
    asm("add.rn.f32x2 %0, %1, %2;" : "=l"(d) : "l"(a), "l"(b));
    return d;
}

// ---------------- sync helpers ----------------
__device__ __forceinline__ int ld_acq(const int* p) {
    int v;
    asm volatile("ld.global.acquire.gpu.b32 %0, [%1];" : "=r"(v) : "l"(p) : "memory");
    return v;
}
__device__ __forceinline__ void spin_ge(const int* p, int v) {
    while (ld_acq(p) < v) { __nanosleep(20); }
}
__device__ __forceinline__ void red_release(int* p, int v) {
    asm volatile("red.release.gpu.global.add.s32 [%0], %1;" :: "l"(p), "r"(v) : "memory");
}

// ---------------- init ----------------
__global__ void init_kernel(const float* __restrict__ in) {
    int tid = blockIdx.x * blockDim.x + threadIdx.x;
    int stride = gridDim.x * blockDim.x;
    if (tid == 0) g_next = 0;
    const int NS = 33*33*BATCH*UNITS;
    for (int idx = tid; idx < NS; idx += stride) {
        g_states[idx] = 0.f;
        g_statesT[idx] = 0.f;
    }
    for (int idx = tid; idx < 2048; idx += stride) {
        if (idx < 1024) g_p1done[idx] = 0; else g_hdone[idx - 1024] = 0;
    }
    const int NX = 1024*64*64;
    for (int idx = tid; idx < NX; idx += stride) {
        int b = idx & 63;
        int c = (idx >> 6) & 63;
        int t = idx >> 12;
        g_xT[idx] = in[(b*64 + c)*1024 + t];
    }
}

// ---------------- main persistent dataflow kernel ----------------
__global__ __launch_bounds__(TPB, 2)
void gru_kernel(const float* __restrict__ W, const float* __restrict__ U_rec,
                const float* __restrict__ bias, const float* __restrict__ W_ij,
                float* __restrict__ out)
{
    extern __shared__ float sm[];
    __shared__ int s_item;
    const int tid = threadIdx.x;

    float* q_s = sm;            // [256][QS] phase-1 q tile
    float* w_s = sm + 17408;    // [256][32] phase-1 W tile (plain)
    // phase-2 aliases:
    float* U_s2 = sm;           // [256][64] U_rec rows 0..191, W_ij rows 192..255
    float* m_s  = sm + 16384;          // [256][16]
    float* h_s  = sm + 16384 + 4096;   // [16][65]

    for (;;) {
        if (tid == 0) s_item = atomicAdd(&g_next, 1);
        __syncthreads();
        int item = s_item;
        if (item >= TOTAL_ITEMS) break;

        // ---- decode item -> (diagonal d, phase, cell, tile) ----
        int d = 0, base = 0, nd = 1, i0 = 0;
        for (d = 0; d < DIAGS; d++) {
            i0 = (d > 31) ? (d - 31) : 0;
            int i1 = (d < 31) ? d : 31;
            nd = i1 - i0 + 1;
            int sz = ITEMS_PER_CELL * nd;
            if (item < base + sz) break;
            base += sz;
        }
        int local = item - base;

        if (local < NP1 * nd) {
            // ========== PHASE 1: gate GEMM tile (64b x 32n x 256k), f32x2 ==========
            int ci = local / NP1, nt = local % NP1;
            int i = i0 + ci, j = d - i;

            // stage W tile (dependency-free) BEFORE the spin: cols [nt*32, nt*32+32)
            {
                const float4* wp = (const float4*)(W + nt*NT);   // row stride 112 f4
                for (int e = tid; e < 2048; e += TPB) {
                    int k = e >> 3, p = e & 7;
                    *(float4*)&w_s[(k << 5) + (p << 2)] = wp[k*112 + p];
                }
            }

            // parallel dependency spins (threads 0..2 poll concurrently)
            if (tid == 0 && i > 0 && j > 0) spin_ge(&g_hdone[(i-1)*32 + (j-1)], NP2);
            if (tid == 1 && i > 0)          spin_ge(&g_hdone[(i-1)*32 + j    ], NP2);
            if (tid == 2 && j > 0)          spin_ge(&g_hdone[ i   *32 + (j-1)], NP2);
            __syncthreads();

            // stage q = [h_top, h_left, h_diag, s_ij], layout [k][b]
            const float* src0 = &g_statesT[((size_t)( i   *33 + (j+1)))*4096];  // h_top
            const float* src1 = &g_statesT[((size_t)((i+1)*33 +  j   ))*4096];  // h_left
            const float* src2 = &g_statesT[((size_t)( i   *33 +  j   ))*4096];  // h_diag
            const float* src3 = &g_xT[(size_t)(i*32 + j)*4096];                 // s_ij
            const float* srcs[4] = {src0, src1, src2, src3};
            #pragma unroll
            for (int p = 0; p < 4; p++) {
                const float4* sp = (const float4*)srcs[p];
                for (int e = tid; e < 1024; e += TPB) {
                    int u = e >> 4, b4 = (e & 15) << 2;
                    *(float4*)&q_s[(p*64 + u)*QS + b4] = sp[e];
                }
            }
            __syncthreads();

            // thread tile: 2 b x 4 n.  warp covers 16 bg x 2 ng.
            // tid bits: [3:0]+[7] -> bg (32), [6:4] -> ng (8)
            const int bg = (tid & 15) | ((tid >> 3) & 16);
            const int ng = (tid >> 4) & 7;
            unsigned long long A00 = 0ull, A01 = 0ull, A10 = 0ull, A11 = 0ull;
            const float* qp = q_s + (bg << 1);
            const float* wp = w_s + (ng << 2);
            #pragma unroll 4
            for (int k = 0; k < 256; k++) {
                float2 qv = *(const float2*)(qp + k*QS);          // (b0,b1)
                ulonglong2 wv = *(const ulonglong2*)(wp + (k << 5)); // (n0,n1),(n2,n3)
                unsigned long long qb0 = pack2(qv.x, qv.x);
                unsigned long long qb1 = pack2(qv.y, qv.y);
                A00 = ffma2(qb0, wv.x, A00);  A01 = ffma2(qb0, wv.y, A01);
                A10 = ffma2(qb1, wv.x, A10);  A11 = ffma2(qb1, wv.y, A11);
            }
            int n0 = nt*NT + (ng << 2);
            unsigned long long b01 = pack2(bias[n0+0], bias[n0+1]);
            unsigned long long b23 = pack2(bias[n0+2], bias[n0+3]);
            A00 = add2(A00, b01);  A01 = add2(A01, b23);
            A10 = add2(A10, b01);  A11 = add2(A11, b23);

            float b0n0,b0n1,b0n2,b0n3,b1n0,b1n1,b1n2,b1n3;
            unpack2(A00, b0n0, b0n1); unpack2(A01, b0n2, b0n3);
            unpack2(A10, b1n0, b1n1); unpack2(A11, b1n2, b1n3);
            float* rz = &g_RZ[(size_t)i * NZ * 64];
            int bb = bg << 1;
            *(float2*)&rz[(n0+0)*64 + bb] = make_float2(b0n0, b1n0);
            *(float2*)&rz[(n0+1)*64 + bb] = make_float2(b0n1, b1n1);
            *(float2*)&rz[(n0+2)*64 + bb] = make_float2(b0n2, b1n2);
            *(float2*)&rz[(n0+3)*64 + bb] = make_float2(b0n3, b1n3);

            __syncthreads();
            if (tid == 0) red_release(&g_p1done[i*32 + j], 1);
        } else {
            // ========== PHASE 2: update GEMM + gates (16b x 64u x 256k) ==========
            int l2 = local - NP1*nd;
            int ci = l2 / NP2, bt = l2 % NP2;
            int i = i0 + ci, j = d - i;

            // stage U (dependency-free) BEFORE the spin
            {
                const float4* up  = (const float4*)U_rec;   // 3072 f4
                const float4* wij = (const float4*)W_ij;    // 1024 f4
                for (int e = tid; e < 4096; e += TPB) {
                    float4 v = (e < 3072) ? up[e] : wij[e - 3072];
                    *(float4*)&U_s2[e << 2] = v;
                }
            }

            if (tid == 0) spin_ge(&g_p1done[i*32 + j], NP1);
            __syncthreads();

            const float* rz  = &g_RZ[(size_t)i * NZ * 64];
            const float* hlT = &g_statesT[((size_t)((i+1)*33 +  j   ))*4096];
            const float* htT = &g_statesT[((size_t)( i   *33 + (j+1)))*4096];
            const float* hdT = &g_statesT[((size_t)( i   *33 +  j   ))*4096];
            const float* xs  = &g_xT[(size_t)(i*32 + j)*4096];

            // m = r * [h_left, h_top, h_diag] (rows 0..191), s_ij (rows 192..255)
            for (int e = tid; e < 4096; e += TPB) {
                int k = e >> 4, b = e & 15;
                int ba = (bt << 4) + b;
                float v;
                if (k < 192) {
                    int g = k >> 6, kk = k & 63;
                    const float* hT = (g == 0) ? hlT : (g == 1) ? htT : hdT;
                    float h = hT[(kk << 6) + ba];
                    float r = rz[(k << 6) + ba];
                    r = 1.f / (1.f + __expf(-r));
                    v = r * h;
                } else {
                    v = xs[((k - 192) << 6) + ba];
                }
                m_s[(k << 4) + b] = v;
            }
            __syncthreads();

            const int u = tid & 63, bsub = tid >> 6;  // 4 consecutive b per thread
            float bj = bias[448 + u];
            float4 acc = {bj, bj, bj, bj};
            const float* mp = m_s + (bsub << 2);
            #pragma unroll 4
            for (int k = 0; k < 256; k++) {
                float  un = U_s2[(k << 6) + u];
                float4 mv = *(const float4*)(mp + (k << 4));
                acc.x += mv.x*un; acc.y += mv.y*un; acc.z += mv.z*un; acc.w += mv.w*un;
            }

            const float* hl = &g_states[((size_t)((i+1)*33 +  j   ))*4096];
            const float* ht = &g_states[((size_t)( i   *33 + (j+1)))*4096];
            const float* hd = &g_states[((size_t)( i   *33 +  j   ))*4096];
            float* hout  = &g_states [((size_t)((i+1)*33 + (j+1)))*4096];
            const float* zb = rz + 192*64;
            float accs[4] = {acc.x, acc.y, acc.z, acc.w};
            bool last = (i == 31) && (j == 31);
            #pragma unroll
            for (int q = 0; q < 4; q++) {
                int bl = (bsub << 2) + q;
                int ba = (bt << 4) + bl;
                float z0 = zb[( u        << 6) + ba];   // zi
                float z1 = zb[((64 + u)  << 6) + ba];   // zl
                float z2 = zb[((128 + u) << 6) + ba];   // zt
                float z3 = zb[((192 + u) << 6) + ba];   // zd
                float mx = fmaxf(fmaxf(z0, z1), fmaxf(z2, z3));
                float e0 = __expf(z0 - mx), e1 = __expf(z1 - mx);
                float e2 = __expf(z2 - mx), e3 = __expf(z3 - mx);
                float inv = 1.f / (e0 + e1 + e2 + e3);
                float hh = tanhf(accs[q]);
                float vl = hl[(ba << 6) + u];
                float vt = ht[(ba << 6) + u];
                float vd = hd[(ba << 6) + u];
                float h  = (e1*vl + e2*vt + e3*vd + e0*hh) * inv;
                hout[(ba << 6) + u] = h;
                h_s[bl*65 + u] = h;
                if (last) out[(ba << 6) + u] = h;
            }
            __syncthreads();
            float* houtT = &g_statesT[((size_t)((i+1)*33 + (j+1)))*4096];
            for (int e = tid; e < 1024; e += TPB) {
                int b = e & 15, uu = e >> 4;
                houtT[(uu << 6) + (bt << 4) + b] = h_s[b*65 + uu];
            }
            __syncthreads();
            if (tid == 0) red_release(&g_hdone[i*32 + j], 1);
        }
    }
}

extern "C" void kernel_launch(void* const* d_in, const int* in_sizes, int n_in,
                              void* d_out, int out_size) {
    const float* inputs = (const float*)d_in[0];
    const float* W      = (const float*)d_in[1];
    const float* U_rec  = (const float*)d_in[2];
    const float* bias   = (const float*)d_in[3];
    const float* W_ij   = (const float*)d_in[4];
    float* out = (float*)d_out;

    cudaFuncSetAttribute(gru_kernel, cudaFuncAttributeMaxDynamicSharedMemorySize, SMEM_BYTES);

    // Deadlock-safe grid sizing: every launched CTA must be resident.
    int occ = 1;
    cudaOccupancyMaxActiveBlocksPerMultiprocessor(&occ, gru_kernel, TPB, SMEM_BYTES);
    if (occ < 1) occ = 1;
    if (occ > 2) occ = 2;
    int grid = 148 * occ;

    init_kernel<<<512, 256>>>(inputs);
    gru_kernel<<<grid, TPB, SMEM_BYTES>>>(W, U_rec, bias, W_ij, out);
}

// round 16
// speedup vs baseline: 1.3324x; 1.1658x over previous
#include <cuda_runtime.h>

#define UNITS 64
#define BATCH 64
#define NZ 448            // gate output cols (192 r + 256 z)
#define NT 32             // n-tile width for phase 1
#define NP1 14            // phase-1 tiles per cell (448/32)
#define NP2 4             // phase-2 tiles per cell (64 b / 16)
#define TPB 256
#define QS 68             // padded row stride for q_s [k][b]
#define DIAGS 63
#define ITEMS_PER_CELL 18
#define TOTAL_ITEMS (ITEMS_PER_CELL*1024)
// smem: phase1 q_s 17408 + w_s 8192 = 25600 floats; phase2 fits in same budget
#define SMEM_FLOATS 25600
#define SMEM_BYTES (SMEM_FLOATS*4)

// ---------------- global scratch ----------------
__device__ float g_states [33*33*BATCH*UNITS];  // h at [i][j][b][u]
__device__ float g_statesT[33*33*BATCH*UNITS];  // h at [i][j][u][b]
__device__ float g_xT[1024*64*64];              // inputs transposed: [t][c][b]
__device__ float g_RZ[32*NZ*BATCH];             // per-row-slot scratch [i][n][b]
__device__ int   g_p1done[1024];
__device__ int   g_hdone [1024];
__device__ int   g_next;

// ---------------- f32x2 helpers ----------------
__device__ __forceinline__ unsigned long long pack2(float x, float y) {
    unsigned long long r;
    asm("mov.b64 %0, {%1,%2};" : "=l"(r) : "f"(x), "f"(y));
    return r;
}
__device__ __forceinline__ void unpack2(unsigned long long v, float& x, float& y) {
    asm("mov.b64 {%0,%1}, %2;" : "=f"(x), "=f"(y) : "l"(v));
}
__device__ __forceinline__ unsigned long long ffma2(unsigned long long a,
                                                    unsigned long long b,
                                                    unsigned long long c) {
    unsigned long long d;
    asm("fma.rn.f32x2 %0, %1, %2, %3;" : "=l"(d) : "l"(a), "l"(b), "l"(c));
    return d;
}
__device__ __forceinline__ unsigned long long add2(unsigned long long a,
                                                   unsigned long long b) {
    unsigned long long d;
    asm("add.rn.f32x2 %0, %1, %2;" : "=l"(d) : "l"(a), "l"(b));
    return d;
}

// ---------------- sync helpers ----------------
__device__ __forceinline__ int ld_acq(const int* p) {
    int v;
    asm volatile("ld.global.acquire.gpu.b32 %0, [%1];" : "=r"(v) : "l"(p) : "memory");
    return v;
}
__device__ __forceinline__ void spin_ge(const int* p, int v) {
    while (ld_acq(p) < v) { }   // hard poll; ~300cyc/poll from L2 latency alone
}
__device__ __forceinline__ void red_release(int* p, int v) {
    asm volatile("red.release.gpu.global.add.s32 [%0], %1;" :: "l"(p), "r"(v) : "memory");
}

// ---------------- init ----------------
__global__ void init_kernel(const float* __restrict__ in) {
    int tid = blockIdx.x * blockDim.x + threadIdx.x;
    int stride = gridDim.x * blockDim.x;
    if (tid == 0) g_next = 0;
    const int NS = 33*33*BATCH*UNITS;
    for (int idx = tid; idx < NS; idx += stride) {
        g_states[idx] = 0.f;
        g_statesT[idx] = 0.f;
    }
    for (int idx = tid; idx < 2048; idx += stride) {
        if (idx < 1024) g_p1done[idx] = 0; else g_hdone[idx - 1024] = 0;
    }
    const int NX = 1024*64*64;
    for (int idx = tid; idx < NX; idx += stride) {
        int b = idx & 63;
        int c = (idx >> 6) & 63;
        int t = idx >> 12;
        g_xT[idx] = in[(b*64 + c)*1024 + t];
    }
}

// ---------------- main persistent dataflow kernel ----------------
__global__ __launch_bounds__(TPB, 2)
void gru_kernel(const float* __restrict__ W, const float* __restrict__ U_rec,
                const float* __restrict__ bias, const float* __restrict__ W_ij,
                float* __restrict__ out)
{
    extern __shared__ float sm[];
    __shared__ int s_item;
    const int tid = threadIdx.x;

    float* q_s = sm;            // [256][QS] phase-1 q tile
    float* w_s = sm + 17408;    // [256][32] phase-1 W tile (plain)
    // phase-2 aliases:
    float* U_s2 = sm;                  // [256][64] U_rec rows 0..191, W_ij rows 192..255
    float* zs   = sm;                  // z stage after GEMM (reuses U region), [256][17]
    float* m_s  = sm + 16384;          // [256][16]
    float* h_s  = sm + 16384 + 4096;   // [16][65]
    float* hb_s = sm + 16384 + 4096 + 1040;  // [3][16][64] epilogue states

    for (;;) {
        if (tid == 0) s_item = atomicAdd(&g_next, 1);
        __syncthreads();
        int item = s_item;
        if (item >= TOTAL_ITEMS) break;

        // ---- decode item -> (diagonal d, cell, within-cell slot) ; cell-major ----
        int d = 0, base = 0, nd = 1, i0 = 0;
        for (d = 0; d < DIAGS; d++) {
            i0 = (d > 31) ? (d - 31) : 0;
            int i1 = (d < 31) ? d : 31;
            nd = i1 - i0 + 1;
            int sz = ITEMS_PER_CELL * nd;
            if (item < base + sz) break;
            base += sz;
        }
        int local = item - base;
        int cell  = local / ITEMS_PER_CELL;
        int w     = local - cell * ITEMS_PER_CELL;
        int i = i0 + cell, j = d - i;

        if (w < NP1) {
            // ========== PHASE 1: gate GEMM tile (64b x 32n x 256k), f32x2 ==========
            int nt = w;

            // stage W tile (dependency-free) BEFORE the spin: cols [nt*32, nt*32+32)
            {
                const float4* wp = (const float4*)(W + nt*NT);   // row stride 112 f4
                for (int e = tid; e < 2048; e += TPB) {
                    int k = e >> 3, p = e & 7;
                    *(float4*)&w_s[(k << 5) + (p << 2)] = wp[k*112 + p];
                }
            }

            // parallel dependency spins (threads 0..2 poll concurrently)
            if (tid == 0 && i > 0 && j > 0) spin_ge(&g_hdone[(i-1)*32 + (j-1)], NP2);
            if (tid == 1 && i > 0)          spin_ge(&g_hdone[(i-1)*32 + j    ], NP2);
            if (tid == 2 && j > 0)          spin_ge(&g_hdone[ i   *32 + (j-1)], NP2);
            __syncthreads();

            // stage q = [h_top, h_left, h_diag, s_ij], layout [k][b]
            const float* src0 = &g_statesT[((size_t)( i   *33 + (j+1)))*4096];  // h_top
            const float* src1 = &g_statesT[((size_t)((i+1)*33 +  j   ))*4096];  // h_left
            const float* src2 = &g_statesT[((size_t)( i   *33 +  j   ))*4096];  // h_diag
            const float* src3 = &g_xT[(size_t)(i*32 + j)*4096];                 // s_ij
            const float* srcs[4] = {src0, src1, src2, src3};
            #pragma unroll
            for (int p = 0; p < 4; p++) {
                const float4* sp = (const float4*)srcs[p];
                for (int e = tid; e < 1024; e += TPB) {
                    int u = e >> 4, b4 = (e & 15) << 2;
                    *(float4*)&q_s[(p*64 + u)*QS + b4] = sp[e];
                }
            }
            __syncthreads();

            // thread tile: 2 b x 4 n.  warp covers 16 bg x 2 ng.
            const int bg = (tid & 15) | ((tid >> 3) & 16);
            const int ng = (tid >> 4) & 7;
            unsigned long long A00 = 0ull, A01 = 0ull, A10 = 0ull, A11 = 0ull;
            const float* qp = q_s + (bg << 1);
            const float* wp = w_s + (ng << 2);
            #pragma unroll 4
            for (int k = 0; k < 256; k++) {
                float2 qv = *(const float2*)(qp + k*QS);             // (b0,b1)
                ulonglong2 wv = *(const ulonglong2*)(wp + (k << 5)); // (n0,n1),(n2,n3)
                unsigned long long qb0 = pack2(qv.x, qv.x);
                unsigned long long qb1 = pack2(qv.y, qv.y);
                A00 = ffma2(qb0, wv.x, A00);  A01 = ffma2(qb0, wv.y, A01);
                A10 = ffma2(qb1, wv.x, A10);  A11 = ffma2(qb1, wv.y, A11);
            }
            int n0 = nt*NT + (ng << 2);
            unsigned long long b01 = pack2(bias[n0+0], bias[n0+1]);
            unsigned long long b23 = pack2(bias[n0+2], bias[n0+3]);
            A00 = add2(A00, b01);  A01 = add2(A01, b23);
            A10 = add2(A10, b01);  A11 = add2(A11, b23);

            float b0n0,b0n1,b0n2,b0n3,b1n0,b1n1,b1n2,b1n3;
            unpack2(A00, b0n0, b0n1); unpack2(A01, b0n2, b0n3);
            unpack2(A10, b1n0, b1n1); unpack2(A11, b1n2, b1n3);
            float* rz = &g_RZ[(size_t)i * NZ * 64];
            int bb = bg << 1;
            *(float2*)&rz[(n0+0)*64 + bb] = make_float2(b0n0, b1n0);
            *(float2*)&rz[(n0+1)*64 + bb] = make_float2(b0n1, b1n1);
            *(float2*)&rz[(n0+2)*64 + bb] = make_float2(b0n2, b1n2);
            *(float2*)&rz[(n0+3)*64 + bb] = make_float2(b0n3, b1n3);

            __syncthreads();
            if (tid == 0) red_release(&g_p1done[i*32 + j], 1);
        } else {
            // ========== PHASE 2: update GEMM + gates (16b x 64u x 256k) ==========
            int bt = w - NP1;

            // stage U (dependency-free) BEFORE the spins
            {
                const float4* up  = (const float4*)U_rec;   // 3072 f4
                const float4* wij = (const float4*)W_ij;    // 1024 f4
                for (int e = tid; e < 4096; e += TPB) {
                    float4 v = (e < 3072) ? up[e] : wij[e - 3072];
                    *(float4*)&U_s2[e << 2] = v;
                }
            }

            // acquire neighbor states (fast path: already satisfied before p1 started)
            if (tid == 0 && i > 0 && j > 0) spin_ge(&g_hdone[(i-1)*32 + (j-1)], NP2);
            if (tid == 1 && i > 0)          spin_ge(&g_hdone[(i-1)*32 + j    ], NP2);
            if (tid == 2 && j > 0)          spin_ge(&g_hdone[ i   *32 + (j-1)], NP2);
            __syncthreads();

            const float* rz  = &g_RZ[(size_t)i * NZ * 64];
            const float* hlT = &g_statesT[((size_t)((i+1)*33 +  j   ))*4096];
            const float* htT = &g_statesT[((size_t)( i   *33 + (j+1)))*4096];
            const float* hdT = &g_statesT[((size_t)( i   *33 +  j   ))*4096];
            const float* xs  = &g_xT[(size_t)(i*32 + j)*4096];
            const float* hl = &g_states[((size_t)((i+1)*33 +  j   ))*4096];
            const float* ht = &g_states[((size_t)( i   *33 + (j+1)))*4096];
            const float* hd = &g_states[((size_t)( i   *33 +  j   ))*4096];

            // pre-stage m_s (h rows w/o sigmoid yet; x rows final) BEFORE p1done spin
            for (int e = tid; e < 4096; e += TPB) {
                int k = e >> 4, b = e & 15;
                int ba = (bt << 4) + b;
                float v;
                if (k < 192) {
                    int g = k >> 6, kk = k & 63;
                    const float* hT = (g == 0) ? hlT : (g == 1) ? htT : hdT;
                    v = hT[(kk << 6) + ba];
                } else {
                    v = xs[((k - 192) << 6) + ba];
                }
                m_s[(k << 4) + b] = v;
            }
            // pre-stage epilogue states: hb_s[g][bl][u]
            for (int e = tid; e < 3072; e += TPB) {
                int g = e >> 10, r = e & 1023;
                int bl = r >> 6, u = r & 63;
                int ba = (bt << 4) + bl;
                const float* hsrc = (g == 0) ? hl : (g == 1) ? ht : hd;
                hb_s[(g << 10) + r] = hsrc[(ba << 6) + u];
            }

            if (tid == 0) spin_ge(&g_p1done[i*32 + j], NP1);
            __syncthreads();

            // fold in sigmoid(r): rows 0..191 only
            for (int e = tid; e < 3072; e += TPB) {
                int k = e >> 4, b = e & 15;
                int ba = (bt << 4) + b;
                float r = rz[(k << 6) + ba];
                m_s[(k << 4) + b] *= 1.f / (1.f + __expf(-r));
            }
            __syncthreads();

            const int u = tid & 63, bsub = tid >> 6;  // 4 consecutive b per thread
            float bj = bias[448 + u];
            float4 acc = {bj, bj, bj, bj};
            const float* mp = m_s + (bsub << 2);
            #pragma unroll 4
            for (int k = 0; k < 256; k++) {
                float  un = U_s2[(k << 6) + u];
                float4 mv = *(const float4*)(mp + (k << 4));
                acc.x += mv.x*un; acc.y += mv.y*un; acc.z += mv.z*un; acc.w += mv.w*un;
            }
            __syncthreads();   // U_s2 no longer needed; zs reuses its space

            // coalesced z stage: zs[(g*64+u)*17 + b] = rz[(192+g*64+u)*64 + (bt*16+b)]
            for (int e = tid; e < 4096; e += TPB) {
                int row = e >> 4, b = e & 15;       // row = g*64+u in 0..255
                zs[row*17 + b] = rz[((192 + row) << 6) + (bt << 4) + b];
            }
            __syncthreads();

            float* hout = &g_states[((size_t)((i+1)*33 + (j+1)))*4096];
            float accs[4] = {acc.x, acc.y, acc.z, acc.w};
            bool last = (i == 31) && (j == 31);
            #pragma unroll
            for (int q = 0; q < 4; q++) {
                int bl = (bsub << 2) + q;
                int ba = (bt << 4) + bl;
                float z0 = zs[( u       )*17 + bl];   // zi
                float z1 = zs[( 64 + u  )*17 + bl];   // zl
                float z2 = zs[(128 + u  )*17 + bl];   // zt
                float z3 = zs[(192 + u  )*17 + bl];   // zd
                float mx = fmaxf(fmaxf(z0, z1), fmaxf(z2, z3));
                float e0 = __expf(z0 - mx), e1 = __expf(z1 - mx);
                float e2 = __expf(z2 - mx), e3 = __expf(z3 - mx);
                float inv = 1.f / (e0 + e1 + e2 + e3);
                float hh = tanhf(accs[q]);
                float vl = hb_s[(0 << 10) + (bl << 6) + u];
                float vt = hb_s[(1 << 10) + (bl << 6) + u];
                float vd = hb_s[(2 << 10) + (bl << 6) + u];
                float h  = (e1*vl + e2*vt + e3*vd + e0*hh) * inv;
                hout[(ba << 6) + u] = h;
                h_s[bl*65 + u] = h;
                if (last) out[(ba << 6) + u] = h;
            }
            __syncthreads();
            float* houtT = &g_statesT[((size_t)((i+1)*33 + (j+1)))*4096];
            for (int e = tid; e < 1024; e += TPB) {
                int b = e & 15, uu = e >> 4;
                houtT[(uu << 6) + (bt << 4) + b] = h_s[b*65 + uu];
            }
            __syncthreads();
            if (tid == 0) red_release(&g_hdone[i*32 + j], 1);
        }
    }
}

extern "C" void kernel_launch(void* const* d_in, const int* in_sizes, int n_in,
                              void* d_out, int out_size) {
    const float* inputs = (const float*)d_in[0];
    const float* W      = (const float*)d_in[1];
    const float* U_rec  = (const float*)d_in[2];
    const float* bias   = (const float*)d_in[3];
    const float* W_ij   = (const float*)d_in[4];
    float* out = (float*)d_out;

    cudaFuncSetAttribute(gru_kernel, cudaFuncAttributeMaxDynamicSharedMemorySize, SMEM_BYTES);

    // Deadlock-safe grid sizing: every launched CTA must be resident.
    int occ = 1;
    cudaOccupancyMaxActiveBlocksPerMultiprocessor(&occ, gru_kernel, TPB, SMEM_BYTES);
    if (occ < 1) occ = 1;
    if (occ > 2) occ = 2;
    int grid = 148 * occ;

    init_kernel<<<512, 256>>>(inputs);
    gru_kernel<<<grid, TPB, SMEM_BYTES>>>(W, U_rec, bias, W_ij, out);
}